// round 14
// baseline (speedup 1.0000x reference)
#include <cuda_runtime.h>
#include <math.h>
#include <stdint.h>

#define HH 128
#define WW 128
#define BATCH 8
#define NPIX (BATCH*HH*WW)

__device__ float g_cost[(size_t)NPIX*96];
__device__ float g_bufA[(size_t)NPIX*128];
__device__ float g_bufB[(size_t)NPIX*128];

__device__ __forceinline__ float mish_f(float v) {
    if (v > 20.f) return v;
    float u = __expf(v);
    float w = u * (u + 2.f);
    return v * __fdividef(w, w + 2.f);
}

__device__ __forceinline__ uint32_t f2tf32(float x) {
    uint32_t r;
    asm("cvt.rna.tf32.f32 %0, %1;" : "=r"(r) : "f"(x));
    return r;
}

__device__ __forceinline__ void mma_tf32(float acc[4],
                                         uint32_t a0, uint32_t a1, uint32_t a2, uint32_t a3,
                                         uint32_t b0, uint32_t b1) {
    asm volatile(
        "mma.sync.aligned.m16n8k8.row.col.f32.tf32.tf32.f32 "
        "{%0,%1,%2,%3}, {%4,%5,%6,%7}, {%8,%9}, {%0,%1,%2,%3};"
        : "+f"(acc[0]), "+f"(acc[1]), "+f"(acc[2]), "+f"(acc[3])
        : "r"(a0), "r"(a1), "r"(a2), "r"(a3), "r"(b0), "r"(b1));
}

// ================= cost volume via tensor cores =================
// Block: 4 rows x 16 px, 384 threads = 12 warps. Warp s = dy+di (0..11):
// all its (dy, di=s-dy) pairs share nxt row (y0+s-4), so B fragments are
// loaded once per ks and reused across dy. D[16x24] per pair; the 9
// diagonals D[i][i+dj] are cost[y0+dy, x0+i, di*9+dj].
// N smem: [12 rows][24 cols][132 ch-stride] tf32 (bank-conflict-free frags).
// P smem: [4*16 px][132] tf32. Stage: per-warp 16x28 for diagonal extract.
#define CNW 38016   // N words
#define CPW 8448    // P words
#define CSW 5376    // stage words (12*448)
#define CSMEM ((CNW + CPW + CSW)*4)   // 207360 bytes

__global__ void __launch_bounds__(384, 1)
cost_mma(const float* __restrict__ prv, const float* __restrict__ nxt,
         float* __restrict__ cost)
{
    extern __shared__ __align__(16) float sm[];
    uint32_t* Nsm = (uint32_t*)sm;
    uint32_t* Psm = Nsm + CNW;
    float*    stg = sm + CNW + CPW + (threadIdx.x >> 5)*448;

    const int b  = blockIdx.z;
    const int y0 = blockIdx.y * 4;
    const int x0 = blockIdx.x * 16;
    const int tid = threadIdx.x;
    const int lane = tid & 31;
    const int s    = tid >> 5;          // warp id = dy+di
    const int kq = lane & 3, rr = lane >> 2;

    // ---- fill N: rows y0-4..y0+7, cols x0-4..x0+19, 128 ch -> tf32 ----
    #pragma unroll 4
    for (int it = 0; it < 24; it++) {
        int idx = tid + it*384;
        int q = idx & 31, cr = idx >> 5;       // cr = row*24 + col
        int row = cr / 24, col = cr - row*24;
        int gy = y0 - 4 + row, gx = x0 - 4 + col;
        float4 v = make_float4(0.f,0.f,0.f,0.f);
        if (gy >= 0 && gy < HH && gx >= 0 && gx < WW)
            v = ((const float4*)nxt)[((size_t)((b*HH+gy)*WW+gx))*32 + q];
        uint4 t;
        t.x = f2tf32(v.x); t.y = f2tf32(v.y); t.z = f2tf32(v.z); t.w = f2tf32(v.w);
        *(uint4*)(Nsm + cr*132 + q*4) = t;
    }
    // ---- fill P: 4 rows x 16 px (always in-bounds) ----
    #pragma unroll
    for (int it = 0; it < 6; it++) {
        int idx = tid + it*384;
        if (idx < 2048) {
            int q = idx & 31, ip = idx >> 5;   // ip = dy*16 + i
            float4 v = ((const float4*)prv)[((size_t)((b*HH + y0 + (ip>>4))*WW + x0 + (ip&15)))*32 + q];
            uint4 t;
            t.x = f2tf32(v.x); t.y = f2tf32(v.y); t.z = f2tf32(v.z); t.w = f2tf32(v.w);
            *(uint4*)(Psm + ip*132 + q*4) = t;
        }
    }
    __syncthreads();

    const int dylo = max(0, s - 8);
    const int dyhi = min(3, s);

    float acc[4][3][4];
    #pragma unroll
    for (int d = 0; d < 4; d++)
        #pragma unroll
        for (int n = 0; n < 3; n++)
            #pragma unroll
            for (int j = 0; j < 4; j++) acc[d][n][j] = 0.f;

    const uint32_t* Nb = Nsm + s*3168 + rr*132 + kq;   // row s local, col rr base
    const uint32_t* Pb = Psm + rr*132 + kq;

    #pragma unroll 4
    for (int ks = 0; ks < 16; ks++) {
        uint32_t b0[3], b1[3];
        #pragma unroll
        for (int nt = 0; nt < 3; nt++) {
            const uint32_t* cp = Nb + nt*8*132 + ks*8;
            b0[nt] = cp[0];
            b1[nt] = cp[4];
        }
        #pragma unroll
        for (int dy = 0; dy < 4; dy++) {
            if (dy < dylo || dy > dyhi) continue;   // warp-uniform
            const uint32_t* ap = Pb + dy*16*132 + ks*8;
            uint32_t a0 = ap[0], a1 = ap[8*132], a2 = ap[4], a3 = ap[8*132 + 4];
            #pragma unroll
            for (int nt = 0; nt < 3; nt++)
                mma_tf32(acc[dy][nt], a0, a1, a2, a3, b0[nt], b1[nt]);
        }
    }

    // ---- extract diagonals: cost[y0+dy, x0+i, di*9+dj] = D[i][i+dj]/128 ----
    const float inv = 1.0f/128.0f;
    const int i = lane & 15, h = lane >> 4;
    for (int dy = dylo; dy <= dyhi; dy++) {
        const int di = s - dy;
        #pragma unroll
        for (int nt = 0; nt < 3; nt++) {
            stg[rr*28 + nt*8 + kq*2]         = acc[dy][nt][0];
            stg[rr*28 + nt*8 + kq*2 + 1]     = acc[dy][nt][1];
            stg[(rr+8)*28 + nt*8 + kq*2]     = acc[dy][nt][2];
            stg[(rr+8)*28 + nt*8 + kq*2 + 1] = acc[dy][nt][3];
        }
        __syncwarp();
        size_t base = ((size_t)((b*HH + y0 + dy)*WW + x0 + i))*96 + di*9;
        #pragma unroll
        for (int dj = 0; dj < 9; dj++)
            if ((dj & 1) == h)
                cost[base + dj] = stg[i*28 + i + dj] * inv;
        __syncwarp();
    }
}

// ================= fused sep-conv layer (mma.sync tf32, warp-pipelined, fp32) =================
template<int CIN, int CINB, int COUT, bool L0M>
__global__ void __launch_bounds__(256, 2)
layer_mma(const float* __restrict__ in, const float* __restrict__ in2,
          const float* __restrict__ inc, const float* __restrict__ dww,
          const float* __restrict__ pw, const float* __restrict__ bias,
          float* __restrict__ out)
{
    constexpr int KCH  = CINB / 32;
    constexpr int NT   = COUT / 8;
    constexpr int BSTP = 8*NT + 4;
    constexpr int BBUF = 32 * BSTP;

    extern __shared__ __align__(16) float smf[];
    char*     smc   = (char*)smf;
    float*    sdw   = smf;                          // 2 x 288
    float*    sbias = smf + 576;                    // 128 (+pad to 704)
    float*    halo  = smf + 704;                    // byte 2816, 2 x 5760 floats
    uint32_t* dwt   = (uint32_t*)(smc + 2816 + 46080);          // 128*36 words
    uint32_t* Bsm   = (uint32_t*)(smc + 2816 + 46080 + 18432);  // 2*BBUF

    const int b  = blockIdx.z;
    const int ty = blockIdx.y * 16;
    const int tx = blockIdx.x * 8;
    const int tid = threadIdx.x;
    const int lane = tid & 31;
    const int wid  = tid >> 5;
    const int kq  = lane & 3;
    const int rr  = lane >> 2;
    const int pc4 = tid & 7;

    if (tid < COUT) sbias[tid] = bias[tid];

    int      hoff[6];
    int      hsz [6];
    uint32_t hdst[6];
    const uint32_t halo_sa = (uint32_t)__cvta_generic_to_shared(halo);
    #pragma unroll
    for (int s = 0; s < 6; s++) {
        int idx = tid + s*256;
        int p = idx >> 3;
        int hy = p / 10, hx = p - hy*10;
        int gy = ty - 1 + hy, gx = tx - 1 + hx;
        bool v = (idx < 1440) && gy >= 0 && gy < HH && gx >= 0 && gx < WW;
        int gyc = min(max(gy, 0), HH-1), gxc = min(max(gx, 0), WW-1);
        hoff[s] = (b*HH + gyc)*WW + gxc;
        hsz [s] = v ? 16 : 0;
        hdst[s] = halo_sa + (uint32_t)p*128 + (uint32_t)pc4*16;
    }

    auto issue_prefetch = [&](int kn, uint32_t bufb) {
        const float4* src; int cof, strd;
        if constexpr (L0M) {
            if (kn < 4)      { src = (const float4*)in;  cof = kn*8;     strd = 32; }
            else if (kn < 8) { src = (const float4*)in2; cof = (kn-4)*8; strd = 32; }
            else             { src = (const float4*)inc; cof = (kn-8)*8; strd = 24; }
        } else {
            src = (const float4*)in; cof = kn*8; strd = CINB/4;
        }
        #pragma unroll
        for (int s = 0; s < 6; s++) {
            if (tid + s*256 < 1440) {
                const void* p = (const void*)(src + (size_t)hoff[s]*strd + cof + pc4);
                asm volatile("cp.async.cg.shared.global [%0], [%1], 16, %2;"
                             :: "r"(hdst[s] + bufb), "l"(p), "r"(hsz[s]) : "memory");
            }
        }
        asm volatile("cp.async.commit_group;" ::: "memory");
    };

    float acc[NT][4];
    #pragma unroll
    for (int n = 0; n < NT; n++)
        #pragma unroll
        for (int j = 0; j < 4; j++) acc[n][j] = 0.f;

    issue_prefetch(0, 0);

    const int dr  = tid >> 4;
    const int dxh = ((tid >> 3) & 1) * 4;

    for (int kc = 0; kc < KCH; kc++) {
        const int k0 = kc * 32;
        uint32_t* Bb = Bsm + (kc & 1) * BBUF;
        float* sdwb  = sdw + (kc & 1) * 288;

        #pragma unroll
        for (int s = 0; s < COUT/8; s++) {
            int j = tid + s*256;
            int kk = j / COUT, co = j - kk*COUT;
            int cb = k0 + kk;
            int corig = L0M ? (cb < 256 ? cb + 81 : cb - 256) : cb;
            bool valid = L0M ? (cb < 337) : true;
            float w = valid ? pw[(size_t)corig*COUT + co] : 0.f;
            Bb[kk*BSTP + (co & 7)*NT + (co >> 3)] = f2tf32(w);
        }
        #pragma unroll
        for (int s = 0; s < 2; s++) {
            int j = tid + s*256;
            if (j < 288) {
                int t = j >> 5, c = j & 31;
                int cb = k0 + c;
                int corig = L0M ? (cb < 256 ? cb + 81 : cb - 256) : cb;
                bool valid = L0M ? (cb < 337) : true;
                sdwb[j] = valid ? dww[t*CIN + corig] : 0.f;
            }
        }
        asm volatile("cp.async.wait_group 0;" ::: "memory");
        __syncthreads();   // the ONLY block barrier per chunk

        {
            const float* hb = halo + (kc & 1) * 5760;
            float4 o0 = make_float4(0.f,0.f,0.f,0.f);
            float4 o1 = o0, o2 = o0, o3 = o0;
            #pragma unroll
            for (int tyy = 0; tyy < 3; tyy++) {
                const float* hr = hb + ((dr + tyy)*10 + dxh)*32 + pc4*4;
                float4 h0 = *(const float4*)(hr + 0*32);
                float4 h1 = *(const float4*)(hr + 1*32);
                float4 h2 = *(const float4*)(hr + 2*32);
                float4 h3 = *(const float4*)(hr + 3*32);
                float4 h4 = *(const float4*)(hr + 4*32);
                float4 h5 = *(const float4*)(hr + 5*32);
                float4 w0 = *(const float4*)(sdwb + (tyy*3+0)*32 + pc4*4);
                float4 w1 = *(const float4*)(sdwb + (tyy*3+1)*32 + pc4*4);
                float4 w2 = *(const float4*)(sdwb + (tyy*3+2)*32 + pc4*4);
                #define DWACC(o, a, b, c) \
                    o.x = fmaf(w0.x, a.x, o.x); o.y = fmaf(w0.y, a.y, o.y); \
                    o.z = fmaf(w0.z, a.z, o.z); o.w = fmaf(w0.w, a.w, o.w); \
                    o.x = fmaf(w1.x, b.x, o.x); o.y = fmaf(w1.y, b.y, o.y); \
                    o.z = fmaf(w1.z, b.z, o.z); o.w = fmaf(w1.w, b.w, o.w); \
                    o.x = fmaf(w2.x, c.x, o.x); o.y = fmaf(w2.y, c.y, o.y); \
                    o.z = fmaf(w2.z, c.z, o.z); o.w = fmaf(w2.w, c.w, o.w);
                DWACC(o0, h0, h1, h2)
                DWACC(o1, h1, h2, h3)
                DWACC(o2, h2, h3, h4)
                DWACC(o3, h3, h4, h5)
                #undef DWACC
            }
            const int pxb = dr*8 + dxh;
            uint4 t0, t1, t2, t3;
            t0.x=f2tf32(o0.x); t0.y=f2tf32(o0.y); t0.z=f2tf32(o0.z); t0.w=f2tf32(o0.w);
            t1.x=f2tf32(o1.x); t1.y=f2tf32(o1.y); t1.z=f2tf32(o1.z); t1.w=f2tf32(o1.w);
            t2.x=f2tf32(o2.x); t2.y=f2tf32(o2.y); t2.z=f2tf32(o2.z); t2.w=f2tf32(o2.w);
            t3.x=f2tf32(o3.x); t3.y=f2tf32(o3.y); t3.z=f2tf32(o3.z); t3.w=f2tf32(o3.w);
            *(uint4*)(dwt + (pxb+0)*36 + pc4*4) = t0;
            *(uint4*)(dwt + (pxb+1)*36 + pc4*4) = t1;
            *(uint4*)(dwt + (pxb+2)*36 + pc4*4) = t2;
            *(uint4*)(dwt + (pxb+3)*36 + pc4*4) = t3;
        }

        if (kc + 1 < KCH)
            issue_prefetch(kc + 1, (uint32_t)(((kc + 1) & 1) * 23040));

        __syncwarp();      // intra-warp handoff: dwt rows 16w..16w+15

        const uint32_t* arow0 = dwt + (wid*16 + rr)*36;
        const uint32_t* arow1 = arow0 + 8*36;
        #pragma unroll
        for (int kb = 0; kb < 4; kb++) {
            const int kof = kb*8 + kq;
            uint32_t a0 = arow0[kof];
            uint32_t a1 = arow1[kof];
            uint32_t a2 = arow0[kof + 4];
            uint32_t a3 = arow1[kof + 4];
            const uint4* b0p = (const uint4*)(Bb + kof*BSTP + rr*NT);
            const uint4* b1p = (const uint4*)(Bb + (kof+4)*BSTP + rr*NT);
            #pragma unroll
            for (int ng = 0; ng < NT/4; ng++) {
                uint4 b0 = b0p[ng];
                uint4 b1 = b1p[ng];
                mma_tf32(acc[ng*4+0], a0,a1,a2,a3, b0.x, b1.x);
                mma_tf32(acc[ng*4+1], a0,a1,a2,a3, b0.y, b1.y);
                mma_tf32(acc[ng*4+2], a0,a1,a2,a3, b0.z, b1.z);
                mma_tf32(acc[ng*4+3], a0,a1,a2,a3, b0.w, b1.w);
            }
        }
    }

    const int px0 = wid*16 + rr;
    const int px1 = px0 + 8;
    const int y0 = ty + (px0 >> 3), x0c = tx + (px0 & 7);
    const int y1 = ty + (px1 >> 3), x1c = tx + (px1 & 7);
    float* op0 = out + (size_t)((b*HH + y0)*WW + x0c)*COUT;
    float* op1 = out + (size_t)((b*HH + y1)*WW + x1c)*COUT;

    #pragma unroll
    for (int nt = 0; nt < NT; nt++) {
        int ch = nt*8 + kq*2;
        float bb0 = sbias[ch], bb1 = sbias[ch+1];
        float2 r0, r1;
        r0.x = mish_f(acc[nt][0] + bb0);
        r0.y = mish_f(acc[nt][1] + bb1);
        r1.x = mish_f(acc[nt][2] + bb0);
        r1.y = mish_f(acc[nt][3] + bb1);
        *(float2*)(op0 + ch) = r0;
        *(float2*)(op1 + ch) = r1;
    }
}

// ================= final flow head (32 -> 2) =================
__global__ void layer5_kernel(const float* __restrict__ in,
                              const float* __restrict__ dww,
                              const float* __restrict__ pw,
                              float* __restrict__ out)
{
    __shared__ __align__(16) float halo[180*36];
    __shared__ __align__(16) float wsm[288 + 64];

    const int b  = blockIdx.z;
    const int ty = blockIdx.y * 16;
    const int tx = blockIdx.x * 8;
    const int tid = threadIdx.x;

    for (int j = tid; j < 288; j += 128) wsm[j] = dww[j];
    if (tid < 64) wsm[288 + tid] = pw[tid];

    for (int idx = tid; idx < 1440; idx += 128) {
        int c4 = idx & 7, p = idx >> 3;
        int hy = p / 10, hx = p - hy*10;
        int gy = ty - 1 + hy, gx = tx - 1 + hx;
        float4 v = make_float4(0.f,0.f,0.f,0.f);
        if (gy >= 0 && gy < HH && gx >= 0 && gx < WW)
            v = ((const float4*)in)[(size_t)((b*HH+gy)*WW+gx)*8 + c4];
        *(float4*)(halo + p*36 + c4*4) = v;
    }
    __syncthreads();

    int y = tid >> 3, x = tid & 7;
    float dwv[32];
    #pragma unroll
    for (int c = 0; c < 32; c++) dwv[c] = 0.f;

    #pragma unroll
    for (int t = 0; t < 9; t++) {
        int hp = ((y + t/3)*10 + (x + t%3))*36;
        #pragma unroll
        for (int c4 = 0; c4 < 8; c4++) {
            float4 h = *(const float4*)(halo + hp + c4*4);
            float4 w = *(const float4*)(wsm + t*32 + c4*4);
            dwv[c4*4+0] = fmaf(w.x, h.x, dwv[c4*4+0]);
            dwv[c4*4+1] = fmaf(w.y, h.y, dwv[c4*4+1]);
            dwv[c4*4+2] = fmaf(w.z, h.z, dwv[c4*4+2]);
            dwv[c4*4+3] = fmaf(w.w, h.w, dwv[c4*4+3]);
        }
    }

    float o0 = 0.f, o1 = 0.f;
    #pragma unroll
    for (int c = 0; c < 32; c++) {
        o0 = fmaf(dwv[c], wsm[288 + c*2 + 0], o0);
        o1 = fmaf(dwv[c], wsm[288 + c*2 + 1], o1);
    }
    int pix = (b*HH + ty + y)*WW + tx + x;
    float2 r; r.x = o0; r.y = o1;
    *(float2*)(out + (size_t)pix*2) = r;
}

// ================= host launch =================
extern "C" void kernel_launch(void* const* d_in, const int* in_sizes, int n_in,
                              void* d_out, int out_size)
{
    const float* prv = (const float*)d_in[0];
    const float* nxt = (const float*)d_in[1];
    const float* dw0 = (const float*)d_in[2];
    const float* pw0 = (const float*)d_in[3];
    const float* b0  = (const float*)d_in[4];
    const float* dw1 = (const float*)d_in[5];
    const float* pw1 = (const float*)d_in[6];
    const float* b1  = (const float*)d_in[7];
    const float* dw2 = (const float*)d_in[8];
    const float* pw2 = (const float*)d_in[9];
    const float* b2  = (const float*)d_in[10];
    const float* dw3 = (const float*)d_in[11];
    const float* pw3 = (const float*)d_in[12];
    const float* b3  = (const float*)d_in[13];
    const float* dw4 = (const float*)d_in[14];
    const float* pw4 = (const float*)d_in[15];
    const float* b4  = (const float*)d_in[16];
    const float* dw5 = (const float*)d_in[17];
    const float* pw5 = (const float*)d_in[18];
    float* out = (float*)d_out;

    float *cost, *bufA, *bufB;
    cudaGetSymbolAddress((void**)&cost, g_cost);
    cudaGetSymbolAddress((void**)&bufA, g_bufA);
    cudaGetSymbolAddress((void**)&bufB, g_bufB);

    const int SL128 = 2816 + 46080 + 18432 + 33792;  // 101120 (NT16)
    const int SL96  = 2816 + 46080 + 18432 + 25600;  // 92928  (NT12)
    const int SL64  = 2816 + 46080 + 18432 + 17408;  // 84736  (NT8)
    const int SL32  = 2816 + 46080 + 18432 + 9216;   // 76544  (NT4)

    cudaFuncSetAttribute(cost_mma, cudaFuncAttributeMaxDynamicSharedMemorySize, CSMEM);
    cudaFuncSetAttribute((const void*)layer_mma<337,352,128,true >, cudaFuncAttributeMaxDynamicSharedMemorySize, SL128);
    cudaFuncSetAttribute((const void*)layer_mma<128,128,128,false>, cudaFuncAttributeMaxDynamicSharedMemorySize, SL128);
    cudaFuncSetAttribute((const void*)layer_mma<128,128, 96,false>, cudaFuncAttributeMaxDynamicSharedMemorySize, SL96);
    cudaFuncSetAttribute((const void*)layer_mma< 96, 96, 64,false>, cudaFuncAttributeMaxDynamicSharedMemorySize, SL64);
    cudaFuncSetAttribute((const void*)layer_mma< 64, 64, 32,false>, cudaFuncAttributeMaxDynamicSharedMemorySize, SL32);

    dim3 cgrid(8, 32, BATCH);   // 16-wide x 4-tall tiles
    cost_mma<<<cgrid, 384, CSMEM>>>(prv, nxt, cost);

    dim3 lgrid(16, 8, BATCH);
    layer_mma<337,352,128,true ><<<lgrid, 256, SL128>>>(prv,  nxt, cost, dw0, pw0, b0, bufA);
    layer_mma<128,128,128,false><<<lgrid, 256, SL128>>>(bufA, nullptr, nullptr, dw1, pw1, b1, bufB);
    layer_mma<128,128, 96,false><<<lgrid, 256, SL96 >>>(bufB, nullptr, nullptr, dw2, pw2, b2, bufA);
    layer_mma< 96, 96, 64,false><<<lgrid, 256, SL64 >>>(bufA, nullptr, nullptr, dw3, pw3, b3, bufB);
    layer_mma< 64, 64, 32,false><<<lgrid, 256, SL32 >>>(bufB, nullptr, nullptr, dw4, pw4, b4, bufA);

    layer5_kernel<<<lgrid, 128>>>(bufA, dw5, pw5, out);
}

// round 15
// speedup vs baseline: 1.5148x; 1.5148x over previous
#include <cuda_runtime.h>
#include <math.h>
#include <stdint.h>

#define HH 128
#define WW 128
#define BATCH 8
#define NPIX (BATCH*HH*WW)

__device__ float g_cost[(size_t)NPIX*96];
__device__ float g_bufA[(size_t)NPIX*128];
__device__ float g_bufB[(size_t)NPIX*128];
__device__ uint32_t g_Bpre[81920];   // pre-permuted tf32 pointwise weights
__device__ float    g_dwpre[6912];   // pre-remapped depthwise weights

__device__ __forceinline__ float mish_f(float v) {
    if (v > 20.f) return v;
    float u = __expf(v);
    float w = u * (u + 2.f);
    return v * __fdividef(w, w + 2.f);
}

__device__ __forceinline__ uint32_t f2tf32(float x) {
    uint32_t r;
    asm("cvt.rna.tf32.f32 %0, %1;" : "=r"(r) : "f"(x));
    return r;
}

__device__ __forceinline__ void mma_tf32(float acc[4],
                                         uint32_t a0, uint32_t a1, uint32_t a2, uint32_t a3,
                                         uint32_t b0, uint32_t b1) {
    asm volatile(
        "mma.sync.aligned.m16n8k8.row.col.f32.tf32.tf32.f32 "
        "{%0,%1,%2,%3}, {%4,%5,%6,%7}, {%8,%9}, {%0,%1,%2,%3};"
        : "+f"(acc[0]), "+f"(acc[1]), "+f"(acc[2]), "+f"(acc[3])
        : "r"(a0), "r"(a1), "r"(a2), "r"(a3), "r"(b0), "r"(b1));
}

// ================= weight prep: permute+convert B, remap dw (once) =================
__global__ void prep_kernel(const float* __restrict__ pw0, const float* __restrict__ dw0,
                            const float* __restrict__ pw1, const float* __restrict__ dw1,
                            const float* __restrict__ pw2, const float* __restrict__ dw2,
                            const float* __restrict__ pw3, const float* __restrict__ dw3,
                            const float* __restrict__ pw4, const float* __restrict__ dw4)
{
    const float* pws[5] = {pw0, pw1, pw2, pw3, pw4};
    const float* dws[5] = {dw0, dw1, dw2, dw3, dw4};
    const int COUTa[5] = {128,128,96,64,32};
    const int CINa [5] = {337,128,128,96,64};
    const int OBa[6] = {0,45056,61440,73728,79872,81920};
    const int ODa[6] = {0,3168,4320,5472,6336,6912};

    int idx = blockIdx.x*256 + threadIdx.x;
    if (idx < 81920) {
        int l = 0;
        while (idx >= OBa[l+1]) l++;
        int rem = idx - OBa[l];
        int COUT = COUTa[l], NT = COUT/8;
        int kc = rem / (32*COUT);
        int r2 = rem - kc*32*COUT;
        int kk = r2 / COUT, co = r2 - kk*COUT;
        int cb = kc*32 + kk;
        int corig = (l == 0) ? (cb < 256 ? cb + 81 : cb - 256) : cb;
        bool valid = (l == 0) ? (cb < 337) : true;
        float w = valid ? pws[l][(size_t)corig*COUT + co] : 0.f;
        g_Bpre[OBa[l] + kc*32*COUT + kk*COUT + (co & 7)*NT + (co >> 3)] = f2tf32(w);
    } else if (idx < 88832) {
        int j2 = idx - 81920;
        int l = 0;
        while (j2 >= ODa[l+1]) l++;
        int rem = j2 - ODa[l];
        int kc = rem / 288, j = rem - kc*288;
        int t = j >> 5, c = j & 31;
        int cb = kc*32 + c;
        int corig = (l == 0) ? (cb < 256 ? cb + 81 : cb - 256) : cb;
        bool valid = (l == 0) ? (cb < 337) : true;
        g_dwpre[ODa[l] + rem] = valid ? dws[l][t*CINa[l] + corig] : 0.f;
    }
}

// ================= cost volume (R13 proven kernel) =================
#define CCS 36
#define CRS 580
__global__ void __launch_bounds__(288, 2)
cost_kernel(const float* __restrict__ prv, const float* __restrict__ nxt,
            float* __restrict__ cost)
{
    extern __shared__ __align__(16) float sm[];
    const int b  = blockIdx.z;
    const int y0 = blockIdx.y * 16;
    const int xb = blockIdx.x * 8;
    const int tid = threadIdx.x;
    const int r  = tid / 18;
    const int q  = (tid % 18) / 9;
    const int di = tid % 9;
    const int xs = q * 4;

    float acc[36];
    #pragma unroll
    for (int k = 0; k < 36; k++) acc[k] = 0.f;

    for (int cc = 0; cc < 4; cc++) {
        if (cc) __syncthreads();
        for (int idx = tid; idx < 3072; idx += 288) {
            int c4 = idx & 7, col = (idx >> 3) & 15, row = idx >> 7;
            int gy = y0 - 4 + row, gx = xb - 4 + col;
            float4 v = make_float4(0.f,0.f,0.f,0.f);
            if (gy >= 0 && gy < HH && gx >= 0 && gx < WW)
                v = ((const float4*)nxt)[((b*HH+gy)*WW+gx)*32 + cc*8 + c4];
            *(float4*)(sm + row*CRS + col*CCS + c4*4) = v;
        }
        __syncthreads();

        const float* nbase = sm + (r + di)*CRS + xs*CCS;
        const float4* prow = (const float4*)prv + (size_t)((b*HH + y0 + r)*WW + xb + xs)*32 + cc*8;

        #pragma unroll 2
        for (int c4 = 0; c4 < 8; c4++) {
            float4 nv[12];
            #pragma unroll
            for (int m = 0; m < 12; m++)
                nv[m] = *(const float4*)(nbase + m*CCS + c4*4);
            #pragma unroll
            for (int i = 0; i < 4; i++) {
                float4 p = prow[i*32 + c4];
                #pragma unroll
                for (int dj = 0; dj < 9; dj++) {
                    float4 nn = nv[i + dj];
                    float s = acc[i*9+dj];
                    s = fmaf(p.x, nn.x, s); s = fmaf(p.y, nn.y, s);
                    s = fmaf(p.z, nn.z, s); s = fmaf(p.w, nn.w, s);
                    acc[i*9+dj] = s;
                }
            }
        }
    }

    const float inv = 1.0f / 128.0f;
    #pragma unroll
    for (int i = 0; i < 4; i++) {
        size_t base = (size_t)((b*HH + y0 + r)*WW + xb + xs + i)*96 + di*9;
        #pragma unroll
        for (int dj = 0; dj < 9; dj++)
            cost[base + dj] = acc[i*9+dj] * inv;
    }
}

// ================= fused sep-conv layer (mma.sync tf32, full cp.async pipeline) =================
// Per chunk: ONE block barrier; depthwise->MMA handoff via __syncwarp.
// Halo + pre-permuted B + pre-remapped dw all fetched via cp.async (one group),
// issued for kc+1 right after depthwise(kc) so the whole fetch hides under MMA.
template<int CINB, int COUT, bool L0M>
__global__ void __launch_bounds__(256, 2)
layer_mma(const float* __restrict__ in, const float* __restrict__ in2,
          const float* __restrict__ inc, const uint32_t* __restrict__ Bpre,
          const float* __restrict__ dwpre, const float* __restrict__ bias,
          float* __restrict__ out)
{
    constexpr int KCH  = CINB / 32;
    constexpr int NT   = COUT / 8;
    constexpr int BSTP = 8*NT + 4;
    constexpr int BBUF = 32 * BSTP;

    extern __shared__ __align__(16) float smf[];
    char*     smc   = (char*)smf;
    float*    sdw   = smf;                          // 2 x 288
    float*    sbias = smf + 576;                    // 128 (+pad to 704)
    float*    halo  = smf + 704;                    // byte 2816, 2 x 5760 floats
    uint32_t* dwt   = (uint32_t*)(smc + 2816 + 46080);          // 128*36 words
    uint32_t* Bsm   = (uint32_t*)(smc + 2816 + 46080 + 18432);  // 2*BBUF

    const int b  = blockIdx.z;
    const int ty = blockIdx.y * 16;
    const int tx = blockIdx.x * 8;
    const int tid = threadIdx.x;
    const int lane = tid & 31;
    const int wid  = tid >> 5;
    const int kq  = lane & 3;
    const int rr  = lane >> 2;
    const int pc4 = tid & 7;

    if (tid < COUT) sbias[tid] = bias[tid];

    // ---- hoisted halo prefetch geometry ----
    int      hoff[6];
    int      hsz [6];
    uint32_t hdst[6];
    const uint32_t halo_sa = (uint32_t)__cvta_generic_to_shared(halo);
    const uint32_t sdw_sa  = (uint32_t)__cvta_generic_to_shared(sdw);
    const uint32_t bsm_sa  = (uint32_t)__cvta_generic_to_shared(Bsm);
    #pragma unroll
    for (int s = 0; s < 6; s++) {
        int idx = tid + s*256;
        int p = idx >> 3;
        int hy = p / 10, hx = p - hy*10;
        int gy = ty - 1 + hy, gx = tx - 1 + hx;
        bool v = (idx < 1440) && gy >= 0 && gy < HH && gx >= 0 && gx < WW;
        int gyc = min(max(gy, 0), HH-1), gxc = min(max(gx, 0), WW-1);
        hoff[s] = (b*HH + gyc)*WW + gxc;
        hsz [s] = v ? 16 : 0;
        hdst[s] = halo_sa + (uint32_t)p*128 + (uint32_t)pc4*16;
    }

    // prefetch EVERYTHING for chunk kn as one cp.async group
    auto issue_all = [&](int kn) {
        const uint32_t hb = (uint32_t)((kn & 1) * 23040);
        // halo
        {
            const float4* src; int cof, strd;
            if constexpr (L0M) {
                if (kn < 4)      { src = (const float4*)in;  cof = kn*8;     strd = 32; }
                else if (kn < 8) { src = (const float4*)in2; cof = (kn-4)*8; strd = 32; }
                else             { src = (const float4*)inc; cof = (kn-8)*8; strd = 24; }
            } else {
                src = (const float4*)in; cof = kn*8; strd = CINB/4;
            }
            #pragma unroll
            for (int s = 0; s < 6; s++) {
                if (tid + s*256 < 1440) {
                    const void* p = (const void*)(src + (size_t)hoff[s]*strd + cof + pc4);
                    asm volatile("cp.async.cg.shared.global [%0], [%1], 16, %2;"
                                 :: "r"(hdst[s] + hb), "l"(p), "r"(hsz[s]) : "memory");
                }
            }
        }
        // B tile: dense rows of COUT words -> smem rows stride BSTP
        {
            const char* bsrc = (const char*)(Bpre + (size_t)kn*32*COUT);
            const uint32_t bdst = bsm_sa + (uint32_t)((kn & 1) * BBUF * 4);
            #pragma unroll
            for (int s = 0; s < COUT/32; s++) {
                int g = tid + s*256;                 // 16B segment id, total 8*COUT
                int row = g / (COUT/4), si = g - row*(COUT/4);
                asm volatile("cp.async.cg.shared.global [%0], [%1], 16;"
                             :: "r"(bdst + (uint32_t)(row*BSTP*4 + si*16)),
                                "l"(bsrc + (size_t)(row*COUT + si*4)*4) : "memory");
            }
        }
        // dw weights: 288 floats = 72 segments
        if (tid < 72) {
            asm volatile("cp.async.ca.shared.global [%0], [%1], 16;"
                         :: "r"(sdw_sa + (uint32_t)((kn & 1)*1152 + tid*16)),
                            "l"((const char*)(dwpre + (size_t)kn*288) + tid*16) : "memory");
        }
        asm volatile("cp.async.commit_group;" ::: "memory");
    };

    float acc[NT][4];
    #pragma unroll
    for (int n = 0; n < NT; n++)
        #pragma unroll
        for (int j = 0; j < 4; j++) acc[n][j] = 0.f;

    issue_all(0);

    const int dr  = tid >> 4;
    const int dxh = ((tid >> 3) & 1) * 4;

    for (int kc = 0; kc < KCH; kc++) {
        uint32_t* Bb = Bsm + (kc & 1) * BBUF;
        float* sdwb  = sdw + (kc & 1) * 288;

        asm volatile("cp.async.wait_group 0;" ::: "memory");
        __syncthreads();   // the ONLY block barrier per chunk

        // ---- depthwise 3x3: 4 adjacent px, one c4 quad, row-window reuse ----
        {
            const float* hb = halo + (kc & 1) * 5760;
            float4 o0 = make_float4(0.f,0.f,0.f,0.f);
            float4 o1 = o0, o2 = o0, o3 = o0;
            #pragma unroll
            for (int tyy = 0; tyy < 3; tyy++) {
                const float* hr = hb + ((dr + tyy)*10 + dxh)*32 + pc4*4;
                float4 h0 = *(const float4*)(hr + 0*32);
                float4 h1 = *(const float4*)(hr + 1*32);
                float4 h2 = *(const float4*)(hr + 2*32);
                float4 h3 = *(const float4*)(hr + 3*32);
                float4 h4 = *(const float4*)(hr + 4*32);
                float4 h5 = *(const float4*)(hr + 5*32);
                float4 w0 = *(const float4*)(sdwb + (tyy*3+0)*32 + pc4*4);
                float4 w1 = *(const float4*)(sdwb + (tyy*3+1)*32 + pc4*4);
                float4 w2 = *(const float4*)(sdwb + (tyy*3+2)*32 + pc4*4);
                #define DWACC(o, a, b, c) \
                    o.x = fmaf(w0.x, a.x, o.x); o.y = fmaf(w0.y, a.y, o.y); \
                    o.z = fmaf(w0.z, a.z, o.z); o.w = fmaf(w0.w, a.w, o.w); \
                    o.x = fmaf(w1.x, b.x, o.x); o.y = fmaf(w1.y, b.y, o.y); \
                    o.z = fmaf(w1.z, b.z, o.z); o.w = fmaf(w1.w, b.w, o.w); \
                    o.x = fmaf(w2.x, c.x, o.x); o.y = fmaf(w2.y, c.y, o.y); \
                    o.z = fmaf(w2.z, c.z, o.z); o.w = fmaf(w2.w, c.w, o.w);
                DWACC(o0, h0, h1, h2)
                DWACC(o1, h1, h2, h3)
                DWACC(o2, h2, h3, h4)
                DWACC(o3, h3, h4, h5)
                #undef DWACC
            }
            const int pxb = dr*8 + dxh;
            uint4 t0, t1, t2, t3;
            t0.x=f2tf32(o0.x); t0.y=f2tf32(o0.y); t0.z=f2tf32(o0.z); t0.w=f2tf32(o0.w);
            t1.x=f2tf32(o1.x); t1.y=f2tf32(o1.y); t1.z=f2tf32(o1.z); t1.w=f2tf32(o1.w);
            t2.x=f2tf32(o2.x); t2.y=f2tf32(o2.y); t2.z=f2tf32(o2.z); t2.w=f2tf32(o2.w);
            t3.x=f2tf32(o3.x); t3.y=f2tf32(o3.y); t3.z=f2tf32(o3.z); t3.w=f2tf32(o3.w);
            *(uint4*)(dwt + (pxb+0)*36 + pc4*4) = t0;
            *(uint4*)(dwt + (pxb+1)*36 + pc4*4) = t1;
            *(uint4*)(dwt + (pxb+2)*36 + pc4*4) = t2;
            *(uint4*)(dwt + (pxb+3)*36 + pc4*4) = t3;
        }

        // ---- prefetch halo+B+dw for chunk kc+1 (hidden under MMA) ----
        if (kc + 1 < KCH)
            issue_all(kc + 1);

        __syncwarp();      // intra-warp handoff: dwt rows 16w..16w+15

        // ---- MMA: 4 k-blocks of 8, B fragments via LDS.128 ----
        const uint32_t* arow0 = dwt + (wid*16 + rr)*36;
        const uint32_t* arow1 = arow0 + 8*36;
        #pragma unroll
        for (int kb = 0; kb < 4; kb++) {
            const int kof = kb*8 + kq;
            uint32_t a0 = arow0[kof];
            uint32_t a1 = arow1[kof];
            uint32_t a2 = arow0[kof + 4];
            uint32_t a3 = arow1[kof + 4];
            const uint4* b0p = (const uint4*)(Bb + kof*BSTP + rr*NT);
            const uint4* b1p = (const uint4*)(Bb + (kof+4)*BSTP + rr*NT);
            #pragma unroll
            for (int ng = 0; ng < NT/4; ng++) {
                uint4 b0 = b0p[ng];
                uint4 b1 = b1p[ng];
                mma_tf32(acc[ng*4+0], a0,a1,a2,a3, b0.x, b1.x);
                mma_tf32(acc[ng*4+1], a0,a1,a2,a3, b0.y, b1.y);
                mma_tf32(acc[ng*4+2], a0,a1,a2,a3, b0.z, b1.z);
                mma_tf32(acc[ng*4+3], a0,a1,a2,a3, b0.w, b1.w);
            }
        }
    }

    // ---- epilogue: bias + mish, float2 stores ----
    const int px0 = wid*16 + rr;
    const int px1 = px0 + 8;
    const int y0 = ty + (px0 >> 3), x0c = tx + (px0 & 7);
    const int y1 = ty + (px1 >> 3), x1c = tx + (px1 & 7);
    float* op0 = out + (size_t)((b*HH + y0)*WW + x0c)*COUT;
    float* op1 = out + (size_t)((b*HH + y1)*WW + x1c)*COUT;

    #pragma unroll
    for (int nt = 0; nt < NT; nt++) {
        int ch = nt*8 + kq*2;
        float bb0 = sbias[ch], bb1 = sbias[ch+1];
        float2 r0, r1;
        r0.x = mish_f(acc[nt][0] + bb0);
        r0.y = mish_f(acc[nt][1] + bb1);
        r1.x = mish_f(acc[nt][2] + bb0);
        r1.y = mish_f(acc[nt][3] + bb1);
        *(float2*)(op0 + ch) = r0;
        *(float2*)(op1 + ch) = r1;
    }
}

// ================= final flow head (32 -> 2) =================
__global__ void layer5_kernel(const float* __restrict__ in,
                              const float* __restrict__ dww,
                              const float* __restrict__ pw,
                              float* __restrict__ out)
{
    __shared__ __align__(16) float halo[180*36];
    __shared__ __align__(16) float wsm[288 + 64];

    const int b  = blockIdx.z;
    const int ty = blockIdx.y * 16;
    const int tx = blockIdx.x * 8;
    const int tid = threadIdx.x;

    for (int j = tid; j < 288; j += 128) wsm[j] = dww[j];
    if (tid < 64) wsm[288 + tid] = pw[tid];

    for (int idx = tid; idx < 1440; idx += 128) {
        int c4 = idx & 7, p = idx >> 3;
        int hy = p / 10, hx = p - hy*10;
        int gy = ty - 1 + hy, gx = tx - 1 + hx;
        float4 v = make_float4(0.f,0.f,0.f,0.f);
        if (gy >= 0 && gy < HH && gx >= 0 && gx < WW)
            v = ((const float4*)in)[(size_t)((b*HH+gy)*WW+gx)*8 + c4];
        *(float4*)(halo + p*36 + c4*4) = v;
    }
    __syncthreads();

    int y = tid >> 3, x = tid & 7;
    float dwv[32];
    #pragma unroll
    for (int c = 0; c < 32; c++) dwv[c] = 0.f;

    #pragma unroll
    for (int t = 0; t < 9; t++) {
        int hp = ((y + t/3)*10 + (x + t%3))*36;
        #pragma unroll
        for (int c4 = 0; c4 < 8; c4++) {
            float4 h = *(const float4*)(halo + hp + c4*4);
            float4 w = *(const float4*)(wsm + t*32 + c4*4);
            dwv[c4*4+0] = fmaf(w.x, h.x, dwv[c4*4+0]);
            dwv[c4*4+1] = fmaf(w.y, h.y, dwv[c4*4+1]);
            dwv[c4*4+2] = fmaf(w.z, h.z, dwv[c4*4+2]);
            dwv[c4*4+3] = fmaf(w.w, h.w, dwv[c4*4+3]);
        }
    }

    float o0 = 0.f, o1 = 0.f;
    #pragma unroll
    for (int c = 0; c < 32; c++) {
        o0 = fmaf(dwv[c], wsm[288 + c*2 + 0], o0);
        o1 = fmaf(dwv[c], wsm[288 + c*2 + 1], o1);
    }
    int pix = (b*HH + ty + y)*WW + tx + x;
    float2 r; r.x = o0; r.y = o1;
    *(float2*)(out + (size_t)pix*2) = r;
}

// ================= host launch =================
extern "C" void kernel_launch(void* const* d_in, const int* in_sizes, int n_in,
                              void* d_out, int out_size)
{
    const float* prv = (const float*)d_in[0];
    const float* nxt = (const float*)d_in[1];
    const float* dw0 = (const float*)d_in[2];
    const float* pw0 = (const float*)d_in[3];
    const float* b0  = (const float*)d_in[4];
    const float* dw1 = (const float*)d_in[5];
    const float* pw1 = (const float*)d_in[6];
    const float* b1  = (const float*)d_in[7];
    const float* dw2 = (const float*)d_in[8];
    const float* pw2 = (const float*)d_in[9];
    const float* b2  = (const float*)d_in[10];
    const float* dw3 = (const float*)d_in[11];
    const float* pw3 = (const float*)d_in[12];
    const float* b3  = (const float*)d_in[13];
    const float* dw4 = (const float*)d_in[14];
    const float* pw4 = (const float*)d_in[15];
    const float* b4  = (const float*)d_in[16];
    const float* dw5 = (const float*)d_in[17];
    const float* pw5 = (const float*)d_in[18];
    float* out = (float*)d_out;

    float *cost, *bufA, *bufB, *dwpre;
    uint32_t* Bpre;
    cudaGetSymbolAddress((void**)&cost,  g_cost);
    cudaGetSymbolAddress((void**)&bufA,  g_bufA);
    cudaGetSymbolAddress((void**)&bufB,  g_bufB);
    cudaGetSymbolAddress((void**)&Bpre,  g_Bpre);
    cudaGetSymbolAddress((void**)&dwpre, g_dwpre);

    const int SC = 24*CRS*4;
    const int SL128 = 2816 + 46080 + 18432 + 33792;  // 101120 (NT16)
    const int SL96  = 2816 + 46080 + 18432 + 25600;  // 92928  (NT12)
    const int SL64  = 2816 + 46080 + 18432 + 17408;  // 84736  (NT8)
    const int SL32  = 2816 + 46080 + 18432 + 9216;   // 76544  (NT4)

    cudaFuncSetAttribute(cost_kernel, cudaFuncAttributeMaxDynamicSharedMemorySize, SC);
    cudaFuncSetAttribute((const void*)layer_mma<352,128,true >, cudaFuncAttributeMaxDynamicSharedMemorySize, SL128);
    cudaFuncSetAttribute((const void*)layer_mma<128,128,false>, cudaFuncAttributeMaxDynamicSharedMemorySize, SL128);
    cudaFuncSetAttribute((const void*)layer_mma<128, 96,false>, cudaFuncAttributeMaxDynamicSharedMemorySize, SL96);
    cudaFuncSetAttribute((const void*)layer_mma< 96, 64,false>, cudaFuncAttributeMaxDynamicSharedMemorySize, SL64);
    cudaFuncSetAttribute((const void*)layer_mma< 64, 32,false>, cudaFuncAttributeMaxDynamicSharedMemorySize, SL32);

    prep_kernel<<<347, 256>>>(pw0, dw0, pw1, dw1, pw2, dw2, pw3, dw3, pw4, dw4);

    dim3 cgrid(16, 8, BATCH);
    cost_kernel<<<cgrid, 288, SC>>>(prv, nxt, cost);

    dim3 lgrid(16, 8, BATCH);
    layer_mma<352,128,true ><<<lgrid, 256, SL128>>>(prv,  nxt, cost, Bpre,         dwpre,        b0, bufA);
    layer_mma<128,128,false><<<lgrid, 256, SL128>>>(bufA, nullptr, nullptr, Bpre + 45056, dwpre + 3168, b1, bufB);
    layer_mma<128, 96,false><<<lgrid, 256, SL96 >>>(bufB, nullptr, nullptr, Bpre + 61440, dwpre + 4320, b2, bufA);
    layer_mma< 96, 64,false><<<lgrid, 256, SL64 >>>(bufA, nullptr, nullptr, Bpre + 73728, dwpre + 5472, b3, bufB);
    layer_mma< 64, 32,false><<<lgrid, 256, SL32 >>>(bufB, nullptr, nullptr, Bpre + 79872, dwpre + 6336, b4, bufA);

    layer5_kernel<<<lgrid, 128>>>(bufA, dw5, pw5, out);
}